// round 13
// baseline (speedup 1.0000x reference)
#include <cuda_runtime.h>
#include <cuda_bf16.h>
#include <math.h>
#include <stdint.h>

#define B_ 64
#define S_ 1024
#define D_ 512
#define H_ 1024
#define NCTA 128
#define NTHR 256
#define NSLAB0 96
#define NSLAB1 128
#define WSLAB 224
#define STB 24576            // stage bytes: 4 W slabs (8KB) + 4 A slabs (16KB)
#define DYN_SMEM (4 * STB)   // 4-slot ring = 96 KB

typedef unsigned char u8;

// ---- persistent device scratch ---------------------------------------------
__device__ __align__(128) u8 g_ximg[(size_t)S_ * 32 * 4096];
__device__ __align__(128) u8 g_wimg[(size_t)NCTA * WSLAB * 2048];
__device__ __align__(128) u8 g_h0img[2][64 * 4096];
__device__ __align__(128) u8 g_h1img[2][64 * 4096];
__device__ unsigned g_bar_count, g_bar_gen;

__device__ __forceinline__ float sig_(float v) { return 1.0f / (1.0f + __expf(-v)); }

__device__ __forceinline__ void bsplit(float x, float y, uint32_t& hw, uint32_t& lw) {
    __nv_bfloat162 h2, l2;
    h2.x = __float2bfloat16_rn(x);
    h2.y = __float2bfloat16_rn(y);
    l2.x = __float2bfloat16_rn(x - __bfloat162float(h2.x));
    l2.y = __float2bfloat16_rn(y - __bfloat162float(h2.y));
    hw = *(uint32_t*)&h2;
    lw = *(uint32_t*)&l2;
}
__device__ __forceinline__ void cp16(unsigned s, const void* g) {
    asm volatile("cp.async.cg.shared.global [%0], [%1], 16;" :: "r"(s), "l"(g));
}
#define MMA(d, a, b) asm volatile( \
    "mma.sync.aligned.m16n8k16.row.col.f32.bf16.bf16.f32 " \
    "{%0,%1,%2,%3},{%4,%5,%6,%7},{%8,%9},{%0,%1,%2,%3};" \
    : "+f"((d)[0]), "+f"((d)[1]), "+f"((d)[2]), "+f"((d)[3]) \
    : "r"((a).x), "r"((a).y), "r"((a).z), "r"((a).w), "r"((b).x), "r"((b).y))

__device__ __forceinline__ void grid_barrier(unsigned& gen) {
    __syncthreads();
    if (threadIdx.x == 0) {
        __threadfence();
        unsigned target = gen + 1u;
        if (atomicAdd(&g_bar_count, 1u) == NCTA - 1) {
            atomicExch(&g_bar_count, 0u);
            __threadfence();
            atomicAdd(&g_bar_gen, 1u);
        } else {
            while (*(volatile unsigned*)&g_bar_gen < target) { }
        }
        __threadfence();
    }
    gen++;
    __syncthreads();
}

// ---- register fragments for one k-slab --------------------------------------
struct Frag {
    uint4 ah0, ah1, al0, al1;
    uint2 bh[4], bl[4];
};

__device__ __forceinline__ void load_frags(Frag& f, const u8* st,
                                           int lane, int ni2, int kspl) {
    const u8* ab = st + kspl * 2048 + lane * 16;
    f.ah0 = *(const uint4*)(ab);
    f.ah1 = *(const uint4*)(ab + 512);
    f.al0 = *(const uint4*)(ab + 1024);
    f.al1 = *(const uint4*)(ab + 1536);
    const u8* bb = st + 8192 + kspl * 4096 + ni2 * 1024 + lane * 8;
#pragma unroll
    for (int n8 = 0; n8 < 4; n8++) {
        f.bh[n8] = *(const uint2*)(bb + n8 * 256);
        f.bl[n8] = *(const uint2*)(bb + 2048 + n8 * 256);
    }
}
__device__ __forceinline__ void do_mma(const Frag& f, float acc[2][4][4]) {
#pragma unroll
    for (int n8 = 0; n8 < 4; n8++) {
        MMA(acc[0][n8], f.ah0, f.bh[n8]);
        MMA(acc[0][n8], f.ah0, f.bl[n8]);
        MMA(acc[0][n8], f.al0, f.bh[n8]);
        MMA(acc[1][n8], f.ah1, f.bh[n8]);
        MMA(acc[1][n8], f.ah1, f.bl[n8]);
        MMA(acc[1][n8], f.al1, f.bh[n8]);
    }
}

// ---- one GEMM phase: k=64 stages, frag ping-pong pipeline -------------------
// warp tile: m32 x n32, k-split 4 (warp handles ks == kspl within each stage)
__device__ __forceinline__ void run_phase(
    const u8* __restrict__ a0, int n0, const u8* __restrict__ a1,
    const u8* __restrict__ wsl, int nch, u8* sstg, unsigned smb,
    int tid, int lane, int ni2, int kspl, float acc[2][4][4]) {
    const int nstg = nch >> 2;
#define STAGE(SC) do { \
        int sc_ = (SC); int sl0_ = sc_ * 4; \
        const u8* as_ = (sl0_ < n0) ? a0 + (size_t)sl0_ * 4096 \
                                    : a1 + (size_t)(sl0_ - n0) * 4096; \
        const u8* ws_ = wsl + (size_t)sl0_ * 2048; \
        unsigned sb_ = smb + (unsigned)((sc_ & 3) * STB); \
        cp16(sb_ + tid * 16, ws_ + tid * 16); \
        cp16(sb_ + (tid + 256) * 16, ws_ + (tid + 256) * 16); \
        cp16(sb_ + 8192 + tid * 16, as_ + tid * 16); \
        cp16(sb_ + 8192 + (tid + 256) * 16, as_ + (tid + 256) * 16); \
        cp16(sb_ + 8192 + (tid + 512) * 16, as_ + (tid + 512) * 16); \
        cp16(sb_ + 8192 + (tid + 768) * 16, as_ + (tid + 768) * 16); \
        asm volatile("cp.async.commit_group;" ::: "memory"); \
    } while (0)

    STAGE(0); STAGE(1); STAGE(2); STAGE(3);
    Frag fr[2];
    asm volatile("cp.async.wait_group 3;" ::: "memory");
    __syncthreads();
    load_frags(fr[0], sstg, lane, ni2, kspl);
    int cur = 0;
#pragma unroll 1
    for (int sc = 0; sc < nstg; sc++) {
        if (sc + 1 < nstg) {
            // complete stage sc+1 (exact outstanding-count at the tail)
            if (sc + 4 <= nstg)      asm volatile("cp.async.wait_group 2;" ::: "memory");
            else if (sc + 3 == nstg) asm volatile("cp.async.wait_group 1;" ::: "memory");
            else                     asm volatile("cp.async.wait_group 0;" ::: "memory");
            __syncthreads();
            // prefetch next stage's fragments; MMAs below hide this latency
            load_frags(fr[cur ^ 1], sstg + ((sc + 1) & 3) * STB, lane, ni2, kspl);
            if (sc + 4 < nstg) STAGE(sc + 4);  // slot sc&3 free after the sync
        }
        do_mma(fr[cur], acc);
        cur ^= 1;
    }
#undef STAGE
}

// ---- epilogue: 4 k-split partials -> gates -> cell update -> h image --------
template <int L>
__device__ __forceinline__ void epi(float acc[2][4][4], float (*sgate)[32 * 68],
                                    const float* sbias, int tid, int lane,
                                    int ni2, int kspl, int j0, int t,
                                    float* cst, u8* himg,
                                    float* out, float* coutp, float* h1f, float* c1f) {
    int rq = lane >> 2, c0 = (lane & 3) * 2;
    float* sgk = sgate[kspl];
#pragma unroll
    for (int mi = 0; mi < 2; mi++)
#pragma unroll
        for (int n8 = 0; n8 < 4; n8++) {
            int cb = (ni2 * 4 + n8) * 8 + c0;
            int r0 = mi * 16 + rq;
            *(float2*)&sgk[r0 * 68 + cb] = make_float2(acc[mi][n8][0], acc[mi][n8][1]);
            *(float2*)&sgk[(r0 + 8) * 68 + cb] = make_float2(acc[mi][n8][2], acc[mi][n8][3]);
        }
    __syncthreads();
    int b = tid >> 2, u2 = (tid & 3) * 2;
    float hv[2], cv[2];
#pragma unroll
    for (int q = 0; q < 2; q++) {
        int u = u2 + q;
        float gi = sbias[u], gf = sbias[8 + u], gg = sbias[16 + u], go = sbias[24 + u];
#pragma unroll
        for (int c = 0; c < 4; c++) {
            gi += sgate[c][u * 68 + b];
            gf += sgate[c][(8 + u) * 68 + b];
            gg += sgate[c][(16 + u) * 68 + b];
            go += sgate[c][(24 + u) * 68 + b];
        }
        float cn = sig_(gf) * cst[q] + sig_(gi) * tanhf(gg);
        cst[q] = cn;
        cv[q] = cn;
        hv[q] = sig_(go) * tanhf(cn);
    }
    uint32_t hw, lw;
    bsplit(hv[0], hv[1], hw, lw);
    int ph = (j0 + u2) >> 1;
    size_t base = (size_t)(ph >> 3) * 4096 + (b >> 3) * 256 +
                  ((b & 7) * 4 + (ph & 3)) * 8 + ((ph & 7) >> 2) * 4;
    *(uint32_t*)(himg + base) = hw;
    *(uint32_t*)(himg + base + 2048) = lw;
    if (L == 1) {
        size_t ob = ((size_t)b * S_ + t) * H_ + j0 + u2;
        *(float2*)(out + ob) = make_float2(hv[0], hv[1]);
        *(float2*)(coutp + ob) = make_float2(cv[0], cv[1]);
        if (t == S_ - 1) {
            *(float2*)(h1f + b * H_ + j0 + u2) = make_float2(hv[0], hv[1]);
            *(float2*)(c1f + b * H_ + j0 + u2) = make_float2(cv[0], cv[1]);
        }
    }
    __syncthreads();
}

// ---- persistent main kernel (prep folded into prologue) ---------------------
__global__ void __launch_bounds__(NTHR, 1) lstm_mma_kernel(
    const float* __restrict__ x,
    const float* __restrict__ Wih0, const float* __restrict__ Whh0,
    const float* __restrict__ Wih1, const float* __restrict__ Whh1,
    const float* __restrict__ bih0, const float* __restrict__ bhh0,
    const float* __restrict__ bih1, const float* __restrict__ bhh1,
    float* __restrict__ out) {
    extern __shared__ __align__(128) u8 sstg[];
    __shared__ float sgate[4][32 * 68];
    __shared__ float sbias[2][32];

    const int tid = threadIdx.x, lane = tid & 31, wid = tid >> 5;
    const int ni2 = wid & 1, kspl = wid >> 1;
    const int cta = blockIdx.x, j0 = cta * 8;
    const unsigned smb = (unsigned)__cvta_generic_to_shared(sstg);

    // ---------- prologue: pack this CTA's weight slice into fragment images --
    {
        const float* Ws[4] = { Wih0, Whh0, Wih1, Whh1 };
        const int kd[4] = { D_, H_, H_, H_ };
        const int soff[4] = { 0, 32, 96, 160 };
#pragma unroll 1
        for (int ms = 0; ms < 4; ms++) {
            int Kdim = kd[ms], Kh = Kdim >> 1;
            const float* W = Ws[ms];
#pragma unroll 1
            for (int i = tid; i < 32 * Kh; i += NTHR) {
                int p = i % Kh, r = i / Kh;
                int grow = (r >> 3) * H_ + j0 + (r & 7);
                float2 v = *(const float2*)(W + (size_t)grow * Kdim + 2 * p);
                uint32_t hw, lw;
                bsplit(v.x, v.y, hw, lw);
                int slab = soff[ms] + (p >> 3);
                size_t base = ((size_t)cta * WSLAB + slab) * 2048 + (r >> 4) * 512 +
                              ((r & 7) * 4 + (p & 3)) * 16 +
                              (((p & 7) >> 2) * 2 + ((r >> 3) & 1)) * 4;
                *(uint32_t*)(g_wimg + base) = hw;
                *(uint32_t*)(g_wimg + base + 1024) = lw;
            }
        }
        // pack x slice: global pair indices [cta*131072, +131072)
        size_t i0 = (size_t)cta * 131072;
#pragma unroll 1
        for (int k = 0; k < 512; k++) {
            size_t i = i0 + (size_t)k * NTHR + tid;
            int p = (int)(i & 255);
            int t = (int)((i >> 8) & 1023);
            int b = (int)(i >> 18);
            float2 v = *(const float2*)(x + ((size_t)b * S_ + t) * D_ + 2 * p);
            uint32_t hw, lw;
            bsplit(v.x, v.y, hw, lw);
            size_t base = ((size_t)t * 32 + (p >> 3)) * 4096 + (b >> 3) * 256 +
                          ((b & 7) * 4 + (p & 3)) * 8 + ((p & 7) >> 2) * 4;
            *(uint32_t*)(g_ximg + base) = hw;
            *(uint32_t*)(g_ximg + base + 2048) = lw;
        }
        // zero initial h images (buffer 0)
        int idx = cta * NTHR + tid;
        if (idx < 16384) ((uint4*)g_h0img[0])[idx] = make_uint4(0, 0, 0, 0);
        else             ((uint4*)g_h1img[0])[idx - 16384] = make_uint4(0, 0, 0, 0);
    }
    if (tid < 64) {
        int L = tid >> 5, g = tid & 31;
        int grow = (g >> 3) * H_ + j0 + (g & 7);
        sbias[L][g] = L ? (bih1[grow] + bhh1[grow]) : (bih0[grow] + bhh0[grow]);
    }
    float cst0[2] = {0.f, 0.f}, cst1[2] = {0.f, 0.f};
    float* coutp = out + (size_t)B_ * S_ * H_;
    float* h1f = out + 2ull * B_ * S_ * H_;
    float* c1f = h1f + (size_t)B_ * H_;

    unsigned gen = *(volatile unsigned*)&g_bar_gen;
    grid_barrier(gen);   // prep complete grid-wide

    const u8* wcta = g_wimg + (size_t)cta * WSLAB * 2048;

    for (int t = 0; t < S_; t++) {
        const int rb = t & 1, wbuf = rb ^ 1;
        {
            float acc[2][4][4] = {};
            run_phase(g_ximg + (size_t)t * 131072, 32, g_h0img[rb], wcta, NSLAB0,
                      sstg, smb, tid, lane, ni2, kspl, acc);
            epi<0>(acc, sgate, sbias[0], tid, lane, ni2, kspl, j0, t, cst0,
                   g_h0img[wbuf], out, coutp, h1f, c1f);
        }
        grid_barrier(gen);
        {
            float acc[2][4][4] = {};
            run_phase(g_h0img[wbuf], 64, g_h1img[rb], wcta + (size_t)NSLAB0 * 2048,
                      NSLAB1, sstg, smb, tid, lane, ni2, kspl, acc);
            epi<1>(acc, sgate, sbias[1], tid, lane, ni2, kspl, j0, t, cst1,
                   g_h1img[wbuf], out, coutp, h1f, c1f);
        }
    }
}

extern "C" void kernel_launch(void* const* d_in, const int* in_sizes, int n_in,
                              void* d_out, int out_size) {
    cudaFuncSetAttribute(lstm_mma_kernel,
                         cudaFuncAttributeMaxDynamicSharedMemorySize, DYN_SMEM);
    lstm_mma_kernel<<<NCTA, NTHR, DYN_SMEM>>>(
        (const float*)d_in[0],
        (const float*)d_in[1], (const float*)d_in[2],
        (const float*)d_in[5], (const float*)d_in[6],
        (const float*)d_in[3], (const float*)d_in[4],
        (const float*)d_in[7], (const float*)d_in[8],
        (float*)d_out);
}

// round 14
// speedup vs baseline: 2.3729x; 2.3729x over previous
#include <cuda_runtime.h>
#include <cuda_bf16.h>
#include <math.h>
#include <stdint.h>

#define B_ 64
#define S_ 1024
#define D_ 512
#define H_ 1024
#define NCTA 128
#define NTHR 256
#define NSLAB0 96
#define NSLAB1 128
#define WSLAB 224
#define STB 24576            // stage bytes: 4 W slabs (8KB) + 4 A slabs (16KB)
#define DYN_SMEM (4 * STB)   // 4-slot ring = 96 KB

typedef unsigned char u8;

// ---- persistent device scratch ---------------------------------------------
__device__ __align__(128) u8 g_ximg[(size_t)S_ * 32 * 4096];
__device__ __align__(128) u8 g_wimg[(size_t)NCTA * WSLAB * 2048];
__device__ __align__(128) u8 g_h0img[2][64 * 4096];
__device__ __align__(128) u8 g_h1img[2][64 * 4096];
__device__ unsigned g_bar_count, g_bar_gen;

__device__ __forceinline__ float sig_(float v) { return 1.0f / (1.0f + __expf(-v)); }

__device__ __forceinline__ void bsplit(float x, float y, uint32_t& hw, uint32_t& lw) {
    __nv_bfloat162 h2, l2;
    h2.x = __float2bfloat16_rn(x);
    h2.y = __float2bfloat16_rn(y);
    l2.x = __float2bfloat16_rn(x - __bfloat162float(h2.x));
    l2.y = __float2bfloat16_rn(y - __bfloat162float(h2.y));
    hw = *(uint32_t*)&h2;
    lw = *(uint32_t*)&l2;
}
__device__ __forceinline__ void cp16(unsigned s, const void* g) {
    asm volatile("cp.async.cg.shared.global [%0], [%1], 16;" :: "r"(s), "l"(g));
}
#define MMA(d, a, b) asm volatile( \
    "mma.sync.aligned.m16n8k16.row.col.f32.bf16.bf16.f32 " \
    "{%0,%1,%2,%3},{%4,%5,%6,%7},{%8,%9},{%0,%1,%2,%3};" \
    : "+f"((d)[0]), "+f"((d)[1]), "+f"((d)[2]), "+f"((d)[3]) \
    : "r"((a).x), "r"((a).y), "r"((a).z), "r"((a).w), "r"((b).x), "r"((b).y))

__device__ __forceinline__ void grid_barrier(unsigned& gen) {
    __syncthreads();
    if (threadIdx.x == 0) {
        __threadfence();
        unsigned target = gen + 1u;
        if (atomicAdd(&g_bar_count, 1u) == NCTA - 1) {
            atomicExch(&g_bar_count, 0u);
            __threadfence();
            atomicAdd(&g_bar_gen, 1u);
        } else {
            while (*(volatile unsigned*)&g_bar_gen < target) { }
        }
        __threadfence();
    }
    gen++;
    __syncthreads();
}

// ---- register fragments for one k-slab --------------------------------------
struct Frag {
    uint4 ah0, ah1, al0, al1;
    uint2 bh[4], bl[4];
};

__device__ __forceinline__ void load_frags(Frag& f, const u8* st,
                                           int lane, int ni2, int kspl) {
    const u8* ab = st + kspl * 2048 + lane * 16;
    f.ah0 = *(const uint4*)(ab);
    f.ah1 = *(const uint4*)(ab + 512);
    f.al0 = *(const uint4*)(ab + 1024);
    f.al1 = *(const uint4*)(ab + 1536);
    const u8* bb = st + 8192 + kspl * 4096 + ni2 * 1024 + lane * 8;
#pragma unroll
    for (int n8 = 0; n8 < 4; n8++) {
        f.bh[n8] = *(const uint2*)(bb + n8 * 256);
        f.bl[n8] = *(const uint2*)(bb + 2048 + n8 * 256);
    }
}
__device__ __forceinline__ void do_mma(const Frag& f, float acc[2][4][4]) {
#pragma unroll
    for (int n8 = 0; n8 < 4; n8++) {
        MMA(acc[0][n8], f.ah0, f.bh[n8]);
        MMA(acc[0][n8], f.ah0, f.bl[n8]);
        MMA(acc[0][n8], f.al0, f.bh[n8]);
        MMA(acc[1][n8], f.ah1, f.bh[n8]);
        MMA(acc[1][n8], f.ah1, f.bl[n8]);
        MMA(acc[1][n8], f.al1, f.bh[n8]);
    }
}

// ---- one GEMM phase: k=64 stages, frag double-buffer (named regs, no spill) -
// warp tile: m32 x n32, k-split 4 (warp handles ks == kspl within each stage)
__device__ __forceinline__ void run_phase(
    const u8* __restrict__ a0, int n0, const u8* __restrict__ a1,
    const u8* __restrict__ wsl, int nch, u8* sstg, unsigned smb,
    int tid, int lane, int ni2, int kspl, float acc[2][4][4]) {
    const int nstg = nch >> 2;   // 24 or 32 -- always even
#define STAGE(SC) do { \
        int sc_ = (SC); int sl0_ = sc_ * 4; \
        const u8* as_ = (sl0_ < n0) ? a0 + (size_t)sl0_ * 4096 \
                                    : a1 + (size_t)(sl0_ - n0) * 4096; \
        const u8* ws_ = wsl + (size_t)sl0_ * 2048; \
        unsigned sb_ = smb + (unsigned)((sc_ & 3) * STB); \
        cp16(sb_ + tid * 16, ws_ + tid * 16); \
        cp16(sb_ + (tid + 256) * 16, ws_ + (tid + 256) * 16); \
        cp16(sb_ + 8192 + tid * 16, as_ + tid * 16); \
        cp16(sb_ + 8192 + (tid + 256) * 16, as_ + (tid + 256) * 16); \
        cp16(sb_ + 8192 + (tid + 512) * 16, as_ + (tid + 512) * 16); \
        cp16(sb_ + 8192 + (tid + 768) * 16, as_ + (tid + 768) * 16); \
        asm volatile("cp.async.commit_group;" ::: "memory"); \
    } while (0)

// one pipeline step: ensure stage SC+1 resident, prefetch its frags into NXT,
// top up the cp.async ring, then MMA on CUR (hides the LDS latency of NXT)
#define PSTEP(SC, CUR, NXT) do { \
        int s_ = (SC); \
        if (s_ + 1 < nstg) { \
            if (s_ + 4 <= nstg)      asm volatile("cp.async.wait_group 2;" ::: "memory"); \
            else if (s_ + 3 == nstg) asm volatile("cp.async.wait_group 1;" ::: "memory"); \
            else                     asm volatile("cp.async.wait_group 0;" ::: "memory"); \
            __syncthreads(); \
            load_frags(NXT, sstg + ((s_ + 1) & 3) * STB, lane, ni2, kspl); \
            if (s_ + 4 < nstg) STAGE(s_ + 4); \
        } \
        do_mma(CUR, acc); \
    } while (0)

    STAGE(0); STAGE(1); STAGE(2); STAGE(3);
    Frag fA, fB;
    asm volatile("cp.async.wait_group 3;" ::: "memory");
    __syncthreads();
    load_frags(fA, sstg, lane, ni2, kspl);
#pragma unroll 1
    for (int sc = 0; sc < nstg; sc += 2) {
        PSTEP(sc, fA, fB);
        PSTEP(sc + 1, fB, fA);
    }
#undef PSTEP
#undef STAGE
}

// ---- epilogue: 4 k-split partials -> gates -> cell update -> h image --------
template <int L>
__device__ __forceinline__ void epi(float acc[2][4][4], float (*sgate)[32 * 68],
                                    const float* sbias, int tid, int lane,
                                    int ni2, int kspl, int j0, int t,
                                    float* cst, u8* himg,
                                    float* out, float* coutp, float* h1f, float* c1f) {
    int rq = lane >> 2, c0 = (lane & 3) * 2;
    float* sgk = sgate[kspl];
#pragma unroll
    for (int mi = 0; mi < 2; mi++)
#pragma unroll
        for (int n8 = 0; n8 < 4; n8++) {
            int cb = (ni2 * 4 + n8) * 8 + c0;
            int r0 = mi * 16 + rq;
            *(float2*)&sgk[r0 * 68 + cb] = make_float2(acc[mi][n8][0], acc[mi][n8][1]);
            *(float2*)&sgk[(r0 + 8) * 68 + cb] = make_float2(acc[mi][n8][2], acc[mi][n8][3]);
        }
    __syncthreads();
    int b = tid >> 2, u2 = (tid & 3) * 2;
    float hv[2], cv[2];
#pragma unroll
    for (int q = 0; q < 2; q++) {
        int u = u2 + q;
        float gi = sbias[u], gf = sbias[8 + u], gg = sbias[16 + u], go = sbias[24 + u];
#pragma unroll
        for (int c = 0; c < 4; c++) {
            gi += sgate[c][u * 68 + b];
            gf += sgate[c][(8 + u) * 68 + b];
            gg += sgate[c][(16 + u) * 68 + b];
            go += sgate[c][(24 + u) * 68 + b];
        }
        float cn = sig_(gf) * cst[q] + sig_(gi) * tanhf(gg);
        cst[q] = cn;
        cv[q] = cn;
        hv[q] = sig_(go) * tanhf(cn);
    }
    uint32_t hw, lw;
    bsplit(hv[0], hv[1], hw, lw);
    int ph = (j0 + u2) >> 1;
    size_t base = (size_t)(ph >> 3) * 4096 + (b >> 3) * 256 +
                  ((b & 7) * 4 + (ph & 3)) * 8 + ((ph & 7) >> 2) * 4;
    *(uint32_t*)(himg + base) = hw;
    *(uint32_t*)(himg + base + 2048) = lw;
    if (L == 1) {
        size_t ob = ((size_t)b * S_ + t) * H_ + j0 + u2;
        *(float2*)(out + ob) = make_float2(hv[0], hv[1]);
        *(float2*)(coutp + ob) = make_float2(cv[0], cv[1]);
        if (t == S_ - 1) {
            *(float2*)(h1f + b * H_ + j0 + u2) = make_float2(hv[0], hv[1]);
            *(float2*)(c1f + b * H_ + j0 + u2) = make_float2(cv[0], cv[1]);
        }
    }
    __syncthreads();
}

// ---- persistent main kernel (prep folded into prologue) ---------------------
__global__ void __launch_bounds__(NTHR, 1) lstm_mma_kernel(
    const float* __restrict__ x,
    const float* __restrict__ Wih0, const float* __restrict__ Whh0,
    const float* __restrict__ Wih1, const float* __restrict__ Whh1,
    const float* __restrict__ bih0, const float* __restrict__ bhh0,
    const float* __restrict__ bih1, const float* __restrict__ bhh1,
    float* __restrict__ out) {
    extern __shared__ __align__(128) u8 sstg[];
    __shared__ float sgate[4][32 * 68];
    __shared__ float sbias[2][32];

    const int tid = threadIdx.x, lane = tid & 31, wid = tid >> 5;
    const int ni2 = wid & 1, kspl = wid >> 1;
    const int cta = blockIdx.x, j0 = cta * 8;
    const unsigned smb = (unsigned)__cvta_generic_to_shared(sstg);

    // ---------- prologue: pack this CTA's weight slice into fragment images --
    {
        const float* Ws[4] = { Wih0, Whh0, Wih1, Whh1 };
        const int kd[4] = { D_, H_, H_, H_ };
        const int soff[4] = { 0, 32, 96, 160 };
#pragma unroll 1
        for (int ms = 0; ms < 4; ms++) {
            int Kdim = kd[ms], Kh = Kdim >> 1;
            const float* W = Ws[ms];
#pragma unroll 1
            for (int i = tid; i < 32 * Kh; i += NTHR) {
                int p = i % Kh, r = i / Kh;
                int grow = (r >> 3) * H_ + j0 + (r & 7);
                float2 v = *(const float2*)(W + (size_t)grow * Kdim + 2 * p);
                uint32_t hw, lw;
                bsplit(v.x, v.y, hw, lw);
                int slab = soff[ms] + (p >> 3);
                size_t base = ((size_t)cta * WSLAB + slab) * 2048 + (r >> 4) * 512 +
                              ((r & 7) * 4 + (p & 3)) * 16 +
                              (((p & 7) >> 2) * 2 + ((r >> 3) & 1)) * 4;
                *(uint32_t*)(g_wimg + base) = hw;
                *(uint32_t*)(g_wimg + base + 1024) = lw;
            }
        }
        // pack x slice: global pair indices [cta*131072, +131072)
        size_t i0 = (size_t)cta * 131072;
#pragma unroll 1
        for (int k = 0; k < 512; k++) {
            size_t i = i0 + (size_t)k * NTHR + tid;
            int p = (int)(i & 255);
            int t = (int)((i >> 8) & 1023);
            int b = (int)(i >> 18);
            float2 v = *(const float2*)(x + ((size_t)b * S_ + t) * D_ + 2 * p);
            uint32_t hw, lw;
            bsplit(v.x, v.y, hw, lw);
            size_t base = ((size_t)t * 32 + (p >> 3)) * 4096 + (b >> 3) * 256 +
                          ((b & 7) * 4 + (p & 3)) * 8 + ((p & 7) >> 2) * 4;
            *(uint32_t*)(g_ximg + base) = hw;
            *(uint32_t*)(g_ximg + base + 2048) = lw;
        }
        // zero initial h images (buffer 0)
        int idx = cta * NTHR + tid;
        if (idx < 16384) ((uint4*)g_h0img[0])[idx] = make_uint4(0, 0, 0, 0);
        else             ((uint4*)g_h1img[0])[idx - 16384] = make_uint4(0, 0, 0, 0);
    }
    if (tid < 64) {
        int L = tid >> 5, g = tid & 31;
        int grow = (g >> 3) * H_ + j0 + (g & 7);
        sbias[L][g] = L ? (bih1[grow] + bhh1[grow]) : (bih0[grow] + bhh0[grow]);
    }
    float cst0[2] = {0.f, 0.f}, cst1[2] = {0.f, 0.f};
    float* coutp = out + (size_t)B_ * S_ * H_;
    float* h1f = out + 2ull * B_ * S_ * H_;
    float* c1f = h1f + (size_t)B_ * H_;

    unsigned gen = *(volatile unsigned*)&g_bar_gen;
    grid_barrier(gen);   // prep complete grid-wide

    const u8* wcta = g_wimg + (size_t)cta * WSLAB * 2048;

    for (int t = 0; t < S_; t++) {
        const int rb = t & 1, wbuf = rb ^ 1;
        {
            float acc[2][4][4] = {};
            run_phase(g_ximg + (size_t)t * 131072, 32, g_h0img[rb], wcta, NSLAB0,
                      sstg, smb, tid, lane, ni2, kspl, acc);
            epi<0>(acc, sgate, sbias[0], tid, lane, ni2, kspl, j0, t, cst0,
                   g_h0img[wbuf], out, coutp, h1f, c1f);
        }
        grid_barrier(gen);
        {
            float acc[2][4][4] = {};
            run_phase(g_h0img[wbuf], 64, g_h1img[rb], wcta + (size_t)NSLAB0 * 2048,
                      NSLAB1, sstg, smb, tid, lane, ni2, kspl, acc);
            epi<1>(acc, sgate, sbias[1], tid, lane, ni2, kspl, j0, t, cst1,
                   g_h1img[wbuf], out, coutp, h1f, c1f);
        }
    }
}

extern "C" void kernel_launch(void* const* d_in, const int* in_sizes, int n_in,
                              void* d_out, int out_size) {
    cudaFuncSetAttribute(lstm_mma_kernel,
                         cudaFuncAttributeMaxDynamicSharedMemorySize, DYN_SMEM);
    lstm_mma_kernel<<<NCTA, NTHR, DYN_SMEM>>>(
        (const float*)d_in[0],
        (const float*)d_in[1], (const float*)d_in[2],
        (const float*)d_in[5], (const float*)d_in[6],
        (const float*)d_in[3], (const float*)d_in[4],
        (const float*)d_in[7], (const float*)d_in[8],
        (float*)d_out);
}

// round 15
// speedup vs baseline: 2.4534x; 1.0339x over previous
#include <cuda_runtime.h>
#include <cuda_bf16.h>
#include <math.h>
#include <stdint.h>

#define B_ 64
#define S_ 1024
#define D_ 512
#define H_ 1024
#define NCTA 128
#define NTHR 512
#define NSLAB0 96
#define NSLAB1 128
#define WSLAB 224
#define STB 24576            // stage bytes: 4 W slabs (8KB) + 4 A slabs (16KB)
#define DYN_SMEM (4 * STB)   // 4-slot ring = 96 KB

typedef unsigned char u8;

// ---- persistent device scratch ---------------------------------------------
__device__ __align__(128) u8 g_ximg[(size_t)S_ * 32 * 4096];
__device__ __align__(128) u8 g_wimg[(size_t)NCTA * WSLAB * 2048];
__device__ __align__(128) u8 g_h0img[2][64 * 4096];
__device__ __align__(128) u8 g_h1img[2][64 * 4096];
__device__ unsigned g_bar_count, g_bar_gen;

__device__ __forceinline__ float sig_(float v) { return 1.0f / (1.0f + __expf(-v)); }

__device__ __forceinline__ void bsplit(float x, float y, uint32_t& hw, uint32_t& lw) {
    __nv_bfloat162 h2, l2;
    h2.x = __float2bfloat16_rn(x);
    h2.y = __float2bfloat16_rn(y);
    l2.x = __float2bfloat16_rn(x - __bfloat162float(h2.x));
    l2.y = __float2bfloat16_rn(y - __bfloat162float(h2.y));
    hw = *(uint32_t*)&h2;
    lw = *(uint32_t*)&l2;
}
__device__ __forceinline__ void cp16(unsigned s, const void* g) {
    asm volatile("cp.async.cg.shared.global [%0], [%1], 16;" :: "r"(s), "l"(g));
}
#define MMA(d, a, b) asm volatile( \
    "mma.sync.aligned.m16n8k16.row.col.f32.bf16.bf16.f32 " \
    "{%0,%1,%2,%3},{%4,%5,%6,%7},{%8,%9},{%0,%1,%2,%3};" \
    : "+f"((d)[0]), "+f"((d)[1]), "+f"((d)[2]), "+f"((d)[3]) \
    : "r"((a).x), "r"((a).y), "r"((a).z), "r"((a).w), "r"((b).x), "r"((b).y))

__device__ __forceinline__ void grid_barrier(unsigned& gen) {
    __syncthreads();
    if (threadIdx.x == 0) {
        __threadfence();
        unsigned target = gen + 1u;
        if (atomicAdd(&g_bar_count, 1u) == NCTA - 1) {
            atomicExch(&g_bar_count, 0u);
            __threadfence();
            atomicAdd(&g_bar_gen, 1u);
        } else {
            while (*(volatile unsigned*)&g_bar_gen < target) { }
        }
        __threadfence();
    }
    gen++;
    __syncthreads();
}

// ---- one GEMM phase: k=64 stages through a 4-slot ring ----------------------
// 16 warps: warp tile m32 x n16; kspl = wid>>2 (k-slab), ni4 = wid&3 (n quarter)
__device__ __forceinline__ void run_phase(
    const u8* __restrict__ a0, int n0, const u8* __restrict__ a1,
    const u8* __restrict__ wsl, int nch, u8* sstg, unsigned smb,
    int tid, int lane, int ni4, int kspl, float acc[2][2][4]) {
    const int nstg = nch >> 2;
#define STAGE(SC) do { \
        int sc_ = (SC); int sl0_ = sc_ * 4; \
        const u8* as_ = (sl0_ < n0) ? a0 + (size_t)sl0_ * 4096 \
                                    : a1 + (size_t)(sl0_ - n0) * 4096; \
        const u8* ws_ = wsl + (size_t)sl0_ * 2048; \
        unsigned sb_ = smb + (unsigned)((sc_ & 3) * STB); \
        cp16(sb_ + tid * 16, ws_ + tid * 16); \
        cp16(sb_ + 8192 + tid * 16, as_ + tid * 16); \
        cp16(sb_ + 8192 + (tid + 512) * 16, as_ + (tid + 512) * 16); \
        asm volatile("cp.async.commit_group;" ::: "memory"); \
    } while (0)

    STAGE(0); STAGE(1); STAGE(2);
#pragma unroll 1
    for (int sc = 0; sc < nstg; sc++) {
        if (sc + 3 < nstg) asm volatile("cp.async.wait_group 2;" ::: "memory");
        else               asm volatile("cp.async.wait_group 0;" ::: "memory");
        __syncthreads();
        const u8* st = sstg + (sc & 3) * STB;
        // A (weights): this warp's k-slab, both m16 halves, hi+lo
        const u8* ab = st + kspl * 2048 + lane * 16;
        uint4 ah0 = *(const uint4*)(ab);
        uint4 ah1 = *(const uint4*)(ab + 512);
        uint4 al0 = *(const uint4*)(ab + 1024);
        uint4 al1 = *(const uint4*)(ab + 1536);
        // B (activations): this warp's n16 quarter of its k-slab, hi+lo
        const u8* bb = st + 8192 + kspl * 4096 + ni4 * 512 + lane * 8;
        uint2 bh[2], bl[2];
#pragma unroll
        for (int j = 0; j < 2; j++) {
            bh[j] = *(const uint2*)(bb + j * 256);
            bl[j] = *(const uint2*)(bb + 2048 + j * 256);
        }
#pragma unroll
        for (int j = 0; j < 2; j++) {
            MMA(acc[0][j], ah0, bh[j]);
            MMA(acc[0][j], ah0, bl[j]);
            MMA(acc[0][j], al0, bh[j]);
            MMA(acc[1][j], ah1, bh[j]);
            MMA(acc[1][j], ah1, bl[j]);
            MMA(acc[1][j], al1, bh[j]);
        }
        if (sc + 3 < nstg) STAGE(sc + 3);
    }
#undef STAGE
}

// ---- epilogue: 4 k-split partials -> gates -> cell update -> h image --------
template <int L>
__device__ __forceinline__ void epi(float acc[2][2][4], float (*sgate)[32 * 68],
                                    const float* sbias, int tid, int lane,
                                    int ni4, int kspl, int j0, int t,
                                    float* cst, u8* himg,
                                    float* out, float* coutp, float* h1f, float* c1f) {
    int rq = lane >> 2, c0 = (lane & 3) * 2;
    float* sgk = sgate[kspl];
#pragma unroll
    for (int mi = 0; mi < 2; mi++)
#pragma unroll
        for (int j = 0; j < 2; j++) {
            int cb = (ni4 * 2 + j) * 8 + c0;
            int r0 = mi * 16 + rq;
            *(float2*)&sgk[r0 * 68 + cb] = make_float2(acc[mi][j][0], acc[mi][j][1]);
            *(float2*)&sgk[(r0 + 8) * 68 + cb] = make_float2(acc[mi][j][2], acc[mi][j][3]);
        }
    __syncthreads();
    if (tid < 256) {
        int b = tid >> 2, u2 = (tid & 3) * 2;
        float hv[2], cv[2];
#pragma unroll
        for (int q = 0; q < 2; q++) {
            int u = u2 + q;
            float gi = sbias[u], gf = sbias[8 + u], gg = sbias[16 + u], go = sbias[24 + u];
#pragma unroll
            for (int c = 0; c < 4; c++) {
                gi += sgate[c][u * 68 + b];
                gf += sgate[c][(8 + u) * 68 + b];
                gg += sgate[c][(16 + u) * 68 + b];
                go += sgate[c][(24 + u) * 68 + b];
            }
            float cn = sig_(gf) * cst[q] + sig_(gi) * tanhf(gg);
            cst[q] = cn;
            cv[q] = cn;
            hv[q] = sig_(go) * tanhf(cn);
        }
        uint32_t hw, lw;
        bsplit(hv[0], hv[1], hw, lw);
        int ph = (j0 + u2) >> 1;
        size_t base = (size_t)(ph >> 3) * 4096 + (b >> 3) * 256 +
                      ((b & 7) * 4 + (ph & 3)) * 8 + ((ph & 7) >> 2) * 4;
        *(uint32_t*)(himg + base) = hw;
        *(uint32_t*)(himg + base + 2048) = lw;
        if (L == 1) {
            size_t ob = ((size_t)b * S_ + t) * H_ + j0 + u2;
            *(float2*)(out + ob) = make_float2(hv[0], hv[1]);
            *(float2*)(coutp + ob) = make_float2(cv[0], cv[1]);
            if (t == S_ - 1) {
                *(float2*)(h1f + b * H_ + j0 + u2) = make_float2(hv[0], hv[1]);
                *(float2*)(c1f + b * H_ + j0 + u2) = make_float2(cv[0], cv[1]);
            }
        }
    }
    __syncthreads();
}

// ---- persistent main kernel (prep folded into prologue) ---------------------
__global__ void __launch_bounds__(NTHR, 1) lstm_mma_kernel(
    const float* __restrict__ x,
    const float* __restrict__ Wih0, const float* __restrict__ Whh0,
    const float* __restrict__ Wih1, const float* __restrict__ Whh1,
    const float* __restrict__ bih0, const float* __restrict__ bhh0,
    const float* __restrict__ bih1, const float* __restrict__ bhh1,
    float* __restrict__ out) {
    extern __shared__ __align__(128) u8 sstg[];
    __shared__ float sgate[4][32 * 68];
    __shared__ float sbias[2][32];

    const int tid = threadIdx.x, lane = tid & 31, wid = tid >> 5;
    const int ni4 = wid & 3, kspl = wid >> 2;
    const int cta = blockIdx.x, j0 = cta * 8;
    const unsigned smb = (unsigned)__cvta_generic_to_shared(sstg);

    // ---------- prologue: pack this CTA's weight slice into fragment images --
    {
        const float* Ws[4] = { Wih0, Whh0, Wih1, Whh1 };
        const int kd[4] = { D_, H_, H_, H_ };
        const int soff[4] = { 0, 32, 96, 160 };
#pragma unroll 1
        for (int ms = 0; ms < 4; ms++) {
            int Kdim = kd[ms], Kh = Kdim >> 1;
            const float* W = Ws[ms];
#pragma unroll 1
            for (int i = tid; i < 32 * Kh; i += NTHR) {
                int p = i % Kh, r = i / Kh;
                int grow = (r >> 3) * H_ + j0 + (r & 7);
                float2 v = *(const float2*)(W + (size_t)grow * Kdim + 2 * p);
                uint32_t hw, lw;
                bsplit(v.x, v.y, hw, lw);
                int slab = soff[ms] + (p >> 3);
                size_t base = ((size_t)cta * WSLAB + slab) * 2048 + (r >> 4) * 512 +
                              ((r & 7) * 4 + (p & 3)) * 16 +
                              (((p & 7) >> 2) * 2 + ((r >> 3) & 1)) * 4;
                *(uint32_t*)(g_wimg + base) = hw;
                *(uint32_t*)(g_wimg + base + 1024) = lw;
            }
        }
        // pack x slice: global pair indices [cta*131072, +131072)
        size_t i0 = (size_t)cta * 131072;
#pragma unroll 1
        for (int k = 0; k < 256; k++) {
            size_t i = i0 + (size_t)k * NTHR + tid;
            int p = (int)(i & 255);
            int t = (int)((i >> 8) & 1023);
            int b = (int)(i >> 18);
            float2 v = *(const float2*)(x + ((size_t)b * S_ + t) * D_ + 2 * p);
            uint32_t hw, lw;
            bsplit(v.x, v.y, hw, lw);
            size_t base = ((size_t)t * 32 + (p >> 3)) * 4096 + (b >> 3) * 256 +
                          ((b & 7) * 4 + (p & 3)) * 8 + ((p & 7) >> 2) * 4;
            *(uint32_t*)(g_ximg + base) = hw;
            *(uint32_t*)(g_ximg + base + 2048) = lw;
        }
        // zero initial h images (buffer 0)
        int idx = cta * NTHR + tid;
        if (idx < 16384)      ((uint4*)g_h0img[0])[idx] = make_uint4(0, 0, 0, 0);
        else if (idx < 32768) ((uint4*)g_h1img[0])[idx - 16384] = make_uint4(0, 0, 0, 0);
    }
    if (tid < 64) {
        int L = tid >> 5, g = tid & 31;
        int grow = (g >> 3) * H_ + j0 + (g & 7);
        sbias[L][g] = L ? (bih1[grow] + bhh1[grow]) : (bih0[grow] + bhh0[grow]);
    }
    float cst0[2] = {0.f, 0.f}, cst1[2] = {0.f, 0.f};
    float* coutp = out + (size_t)B_ * S_ * H_;
    float* h1f = out + 2ull * B_ * S_ * H_;
    float* c1f = h1f + (size_t)B_ * H_;

    unsigned gen = *(volatile unsigned*)&g_bar_gen;
    grid_barrier(gen);   // prep complete grid-wide

    const u8* wcta = g_wimg + (size_t)cta * WSLAB * 2048;

    for (int t = 0; t < S_; t++) {
        const int rb = t & 1, wbuf = rb ^ 1;
        {
            float acc[2][2][4] = {};
            run_phase(g_ximg + (size_t)t * 131072, 32, g_h0img[rb], wcta, NSLAB0,
                      sstg, smb, tid, lane, ni4, kspl, acc);
            epi<0>(acc, sgate, sbias[0], tid, lane, ni4, kspl, j0, t, cst0,
                   g_h0img[wbuf], out, coutp, h1f, c1f);
        }
        grid_barrier(gen);
        {
            float acc[2][2][4] = {};
            run_phase(g_h0img[wbuf], 64, g_h1img[rb], wcta + (size_t)NSLAB0 * 2048,
                      NSLAB1, sstg, smb, tid, lane, ni4, kspl, acc);
            epi<1>(acc, sgate, sbias[1], tid, lane, ni4, kspl, j0, t, cst1,
                   g_h1img[wbuf], out, coutp, h1f, c1f);
        }
    }
}

extern "C" void kernel_launch(void* const* d_in, const int* in_sizes, int n_in,
                              void* d_out, int out_size) {
    cudaFuncSetAttribute(lstm_mma_kernel,
                         cudaFuncAttributeMaxDynamicSharedMemorySize, DYN_SMEM);
    lstm_mma_kernel<<<NCTA, NTHR, DYN_SMEM>>>(
        (const float*)d_in[0],
        (const float*)d_in[1], (const float*)d_in[2],
        (const float*)d_in[5], (const float*)d_in[6],
        (const float*)d_in[3], (const float*)d_in[4],
        (const float*)d_in[7], (const float*)d_in[8],
        (float*)d_out);
}